// round 1
// baseline (speedup 1.0000x reference)
#include <cuda_runtime.h>

// ---------------------------------------------------------------------------
// image_prj: D = dct2(image) [2048x2048, ortho] -> pad to 2198x2198 ->
// 32-angle radon (bilinear, WRAP) -> lines^T / max
// ---------------------------------------------------------------------------

#define MM    2048
#define PP    2198
#define PADB  75
#define NANG  32
#define TOT   (NANG * PP)      // 70336
#define YSPLIT 4
#define YCHUNK 550             // 4*550 = 2200 >= 2198

__device__ float    g_C[MM * MM];        // DCT matrix
__device__ float    g_tmp[MM * MM];      // C @ X
__device__ float    g_pad[PP * PP];      // padded D = (C@X) @ C^T
__device__ float    g_lpart[YSPLIT * TOT];
__device__ float    g_lines[TOT];
__device__ unsigned g_maxbits;           // ordered-float max bits

// ---------------------------------------------------------------------------
__global__ void init_kernel() {
    int idx = blockIdx.x * 256 + threadIdx.x;
    if (idx < PP * PP) g_pad[idx] = 0.0f;
    if (idx == 0) g_maxbits = 0u;        // ordered-min (below -inf)
}

// C[k,n] = s_k * cos(pi*(n+0.5)*k/N); exact phase reduction mod 2 (mask 8191)
__global__ void gen_dct_kernel() {
    int idx = blockIdx.x * 256 + threadIdx.x;
    if (idx >= MM * MM) return;
    int k = idx >> 11;
    int n = idx & (MM - 1);
    int r = ((2 * n + 1) * k) & (4 * MM - 1);     // phase in units of pi/(2N)
    float t = (float)r * (1.0f / (2.0f * MM));    // in [0,2)
    float c = cospif(t);
    float s = (k == 0) ? 0.022097086912079608f    // sqrt(1/2048)
                       : 0.03125f;                // sqrt(2/2048) = 1/32 exact
    g_C[idx] = s * c;
}

// ---------------------------------------------------------------------------
// 128x128x8 double-buffered fp32 GEMM, 256 threads, 8x8 per thread.
// TRANSB=false: D = A @ B          (B row-major [K,N])
// TRANSB=true : D = A @ B^T        (B row-major [N,K])
// Output written at (offr, offc) into a matrix of leading dim ldd.
template <bool TRANSB>
__device__ __forceinline__ void sgemm_body(const float* __restrict__ A,
                                           const float* __restrict__ B,
                                           float* __restrict__ D,
                                           int offr, int offc, int ldd)
{
    const int K = MM, N = MM;
    __shared__ float As[2][8][128];
    __shared__ float Bs[2][8][128];

    int tid = threadIdx.x;
    int m0  = blockIdx.y * 128;
    int n0  = blockIdx.x * 128;

    int am = tid >> 1;            // A: row within tile
    int ak = (tid & 1) << 2;      // A: k quad
    int bk, bn;
    if (!TRANSB) { bk = tid >> 5; bn = (tid & 31) << 2; }
    else         { bn = tid >> 1; bk = (tid & 1)  << 2; }

    float acc[8][8];
#pragma unroll
    for (int i = 0; i < 8; i++)
#pragma unroll
        for (int j = 0; j < 8; j++) acc[i][j] = 0.0f;

    int tm = (tid >> 4) << 3;
    int tn = (tid & 15) << 3;

    // prologue
    float4 a4 = *(const float4*)&A[(size_t)(m0 + am) * K + ak];
    float4 b4 = TRANSB ? *(const float4*)&B[(size_t)(n0 + bn) * K + bk]
                       : *(const float4*)&B[(size_t)bk * N + n0 + bn];
    As[0][ak + 0][am] = a4.x; As[0][ak + 1][am] = a4.y;
    As[0][ak + 2][am] = a4.z; As[0][ak + 3][am] = a4.w;
    if (TRANSB) {
        Bs[0][bk + 0][bn] = b4.x; Bs[0][bk + 1][bn] = b4.y;
        Bs[0][bk + 2][bn] = b4.z; Bs[0][bk + 3][bn] = b4.w;
    } else {
        *(float4*)&Bs[0][bk][bn] = b4;
    }
    __syncthreads();

    int cur = 0;
    for (int kt = 0; kt < K / 8; ++kt) {
        int knext = (kt + 1) * 8;
        if (knext < K) {
            a4 = *(const float4*)&A[(size_t)(m0 + am) * K + knext + ak];
            b4 = TRANSB ? *(const float4*)&B[(size_t)(n0 + bn) * K + knext + bk]
                        : *(const float4*)&B[(size_t)(knext + bk) * N + n0 + bn];
        }
#pragma unroll
        for (int k = 0; k < 8; ++k) {
            float af[8], bf[8];
            *(float4*)&af[0] = *(const float4*)&As[cur][k][tm];
            *(float4*)&af[4] = *(const float4*)&As[cur][k][tm + 4];
            *(float4*)&bf[0] = *(const float4*)&Bs[cur][k][tn];
            *(float4*)&bf[4] = *(const float4*)&Bs[cur][k][tn + 4];
#pragma unroll
            for (int i = 0; i < 8; i++)
#pragma unroll
                for (int j = 0; j < 8; j++)
                    acc[i][j] = fmaf(af[i], bf[j], acc[i][j]);
        }
        if (knext < K) {
            int nxt = cur ^ 1;
            As[nxt][ak + 0][am] = a4.x; As[nxt][ak + 1][am] = a4.y;
            As[nxt][ak + 2][am] = a4.z; As[nxt][ak + 3][am] = a4.w;
            if (TRANSB) {
                Bs[nxt][bk + 0][bn] = b4.x; Bs[nxt][bk + 1][bn] = b4.y;
                Bs[nxt][bk + 2][bn] = b4.z; Bs[nxt][bk + 3][bn] = b4.w;
            } else {
                *(float4*)&Bs[nxt][bk][bn] = b4;
            }
            __syncthreads();
            cur = nxt;
        }
    }

#pragma unroll
    for (int i = 0; i < 8; i++)
#pragma unroll
        for (int j = 0; j < 8; j++)
            D[(size_t)(m0 + tm + i + offr) * ldd + (n0 + tn + j + offc)] = acc[i][j];
}

__global__ __launch_bounds__(256, 2) void gemm1_kernel(const float* __restrict__ img) {
    sgemm_body<false>(g_C, img, g_tmp, 0, 0, MM);        // tmp = C @ X
}
__global__ __launch_bounds__(256, 2) void gemm2_kernel() {
    sgemm_body<true>(g_tmp, g_C, g_pad, PADB, PADB, PP); // pad[75:,75:] = tmp @ C^T
}

// ---------------------------------------------------------------------------
// Radon: for each (angle a, output col x), sum over y of bilinear sample at
// rotated coords with WRAP. Deterministic partials over YSPLIT y-chunks.
__global__ void radon_kernel() {
    int a = blockIdx.y;
    int x = blockIdx.x * 128 + threadIdx.x;
    if (x >= PP) return;

    float ang = (float)(3.141592653589793 * (double)a / 31.0);
    float ca = cosf(ang);
    float sa = sinf(ang);
    const float cen = (float)(PP / 2);   // 1099
    float c1 = cen * (ca + sa - 1.0f);
    float c2 = cen * (ca - sa - 1.0f);

    float xf = (float)x;
    float bx = ca * xf - c1;     // x_in = bx + sa*y
    float by = -sa * xf - c2;    // y_in = by + ca*y

    int ys = blockIdx.z * YCHUNK;
    int ye = min(PP, ys + YCHUNK);

    float acc = 0.0f;
    for (int y = ys; y < ye; ++y) {
        float yf  = (float)y;
        float xin = sa * yf + bx;
        float yin = ca * yf + by;
        float fx = floorf(xin);
        float fy = floorf(yin);
        float wx = xin - fx;
        float wy = yin - fy;
        int x0 = (int)fx % PP; if (x0 < 0) x0 += PP;
        int y0 = (int)fy % PP; if (y0 < 0) y0 += PP;
        int x1 = x0 + 1; if (x1 == PP) x1 = 0;
        int y1 = y0 + 1; if (y1 == PP) y1 = 0;
        const float* r0 = g_pad + (size_t)y0 * PP;
        const float* r1 = g_pad + (size_t)y1 * PP;
        float v00 = __ldg(r0 + x0);
        float v01 = __ldg(r0 + x1);
        float v10 = __ldg(r1 + x0);
        float v11 = __ldg(r1 + x1);
        float top = (1.0f - wx) * v00 + wx * v01;
        float bot = (1.0f - wx) * v10 + wx * v11;
        acc += (1.0f - wy) * top + wy * bot;
    }
    g_lpart[(size_t)blockIdx.z * TOT + a * PP + x] = acc;
}

// Sum partials -> g_lines, and fold a global max (ordered-bits atomicMax).
__global__ void reduce_max_kernel() {
    __shared__ float smax[256];
    int idx = blockIdx.x * 256 + threadIdx.x;
    float v = -__int_as_float(0x7f800000);   // -inf
    if (idx < TOT) {
        float s = 0.0f;
#pragma unroll
        for (int p = 0; p < YSPLIT; p++) s += g_lpart[(size_t)p * TOT + idx];
        g_lines[idx] = s;
        v = s;
    }
    smax[threadIdx.x] = v;
    __syncthreads();
    for (int o = 128; o > 0; o >>= 1) {
        if (threadIdx.x < o)
            smax[threadIdx.x] = fmaxf(smax[threadIdx.x], smax[threadIdx.x + o]);
        __syncthreads();
    }
    if (threadIdx.x == 0) {
        unsigned u = __float_as_uint(smax[0]);
        unsigned enc = (u & 0x80000000u) ? ~u : (u | 0x80000000u);
        atomicMax(&g_maxbits, enc);
    }
}

// out[x*32 + a] = lines[a*PP + x] / max
__global__ void normalize_kernel(float* __restrict__ out) {
    int idx = blockIdx.x * 256 + threadIdx.x;
    if (idx >= TOT) return;
    unsigned u = g_maxbits;
    float mx = (u & 0x80000000u) ? __uint_as_float(u & 0x7fffffffu)
                                 : __uint_as_float(~u);
    int x = idx >> 5;
    int a = idx & 31;
    out[idx] = g_lines[a * PP + x] / mx;
}

// ---------------------------------------------------------------------------
extern "C" void kernel_launch(void* const* d_in, const int* in_sizes, int n_in,
                              void* d_out, int out_size) {
    const float* img = (const float*)d_in[0];
    float* out = (float*)d_out;

    init_kernel<<<(PP * PP + 255) / 256, 256>>>();
    gen_dct_kernel<<<(MM * MM + 255) / 256, 256>>>();

    dim3 gg(MM / 128, MM / 128);
    gemm1_kernel<<<gg, 256>>>(img);
    gemm2_kernel<<<gg, 256>>>();

    dim3 rg((PP + 127) / 128, NANG, YSPLIT);
    radon_kernel<<<rg, 128>>>();

    reduce_max_kernel<<<(TOT + 255) / 256, 256>>>();
    normalize_kernel<<<(TOT + 255) / 256, 256>>>(out);
}

// round 3
// speedup vs baseline: 1.7248x; 1.7248x over previous
#include <cuda_runtime.h>
#include <cuda_bf16.h>
#include <cstdint>

// ---------------------------------------------------------------------------
// image_prj: D = dct2(image) [2048x2048, ortho] -> pad to 2198x2198 ->
// 32-angle radon (bilinear, WRAP) -> lines^T / max
// GEMMs via mma.sync bf16x3 split (compute_103-safe HMMA), fp32 reg accum.
// ---------------------------------------------------------------------------

#define MM    2048
#define PP    2198
#define PADB  75
#define NANG  32
#define TOT   (NANG * PP)
#define YSPLIT 4
#define YCHUNK 550

__device__ __nv_bfloat16 g_Ch[MM * MM], g_Cl[MM * MM];    // DCT matrix hi/lo
__device__ __nv_bfloat16 g_XTh[MM * MM], g_XTl[MM * MM];  // image^T hi/lo
__device__ __nv_bfloat16 g_Th[MM * MM], g_Tl[MM * MM];    // tmp = C@X hi/lo
__device__ float    g_pad[PP * PP];
__device__ float    g_lpart[YSPLIT * TOT];
__device__ float    g_lines[TOT];
__device__ unsigned g_maxbits;

// ------------------------------ PTX helpers -------------------------------
__device__ __forceinline__ uint32_t smem_u32(const void* p) {
    uint32_t a;
    asm("{ .reg .u64 t; cvta.to.shared.u64 t, %1; cvt.u32.u64 %0, t; }"
        : "=r"(a) : "l"(p));
    return a;
}
#define CP_COMMIT() asm volatile("cp.async.commit_group;" ::: "memory")
#define CP_WAIT(n)  asm volatile("cp.async.wait_group %0;" :: "n"(n) : "memory")

__device__ __forceinline__ void cp16(uint32_t dst, const void* src) {
    asm volatile("cp.async.cg.shared.global [%0], [%1], 16;"
                 :: "r"(dst), "l"(src) : "memory");
}
__device__ __forceinline__ void ldsm4(uint32_t& r0, uint32_t& r1,
                                      uint32_t& r2, uint32_t& r3, uint32_t a) {
    asm volatile("ldmatrix.sync.aligned.m8n8.x4.shared.b16 {%0,%1,%2,%3}, [%4];"
                 : "=r"(r0), "=r"(r1), "=r"(r2), "=r"(r3) : "r"(a));
}
__device__ __forceinline__ void mma16816(float* d, const uint32_t* a,
                                         const uint32_t* b) {
    asm volatile("mma.sync.aligned.m16n8k16.row.col.f32.bf16.bf16.f32 "
                 "{%0,%1,%2,%3}, {%4,%5,%6,%7}, {%8,%9}, {%0,%1,%2,%3};"
                 : "+f"(d[0]), "+f"(d[1]), "+f"(d[2]), "+f"(d[3])
                 : "r"(a[0]), "r"(a[1]), "r"(a[2]), "r"(a[3]),
                   "r"(b[0]), "r"(b[1]));
}
__device__ __forceinline__ uint32_t sw128(uint32_t b) { return b ^ ((b >> 3) & 0x70); }

// --------------------------- small prep kernels ---------------------------
__global__ void init_kernel() {
    int idx = blockIdx.x * 256 + threadIdx.x;
    if (idx < PP * PP) g_pad[idx] = 0.0f;
    if (idx == 0) g_maxbits = 0u;
}

__global__ void gen_dct_kernel() {
    int idx = blockIdx.x * 256 + threadIdx.x;
    if (idx >= MM * MM) return;
    int k = idx >> 11;
    int n = idx & (MM - 1);
    int r = ((2 * n + 1) * k) & (4 * MM - 1);
    float t = (float)r * (1.0f / (2.0f * MM));
    float c = cospif(t);
    float s = (k == 0) ? 0.022097086912079608f : 0.03125f;
    float v = s * c;
    __nv_bfloat16 h = __float2bfloat16(v);
    g_Ch[idx] = h;
    g_Cl[idx] = __float2bfloat16(v - __bfloat162float(h));
}

__global__ void transpose_split_kernel(const float* __restrict__ img) {
    __shared__ float tile[32][33];
    int bx = blockIdx.x * 32, by = blockIdx.y * 32;
    int tx = threadIdx.x, ty = threadIdx.y;
#pragma unroll
    for (int i = 0; i < 4; i++)
        tile[ty + i * 8][tx] = img[(size_t)(by + ty + i * 8) * MM + bx + tx];
    __syncthreads();
#pragma unroll
    for (int i = 0; i < 4; i++) {
        float v = tile[tx][ty + i * 8];
        __nv_bfloat16 h = __float2bfloat16(v);
        size_t o = (size_t)(bx + ty + i * 8) * MM + by + tx;
        g_XTh[o] = h;
        g_XTl[o] = __float2bfloat16(v - __bfloat162float(h));
    }
}

// ------------------------------ HMMA GEMM ---------------------------------
// D[m,n] = sum_k A[m,k] * B[n,k], bf16x3 split, fp32 accum.
// CTA 128x128, K-chunk 64, 3-stage cp.async pipeline, 8 warps (2m x 4n),
// warp tile 64x32 (4 m16-tiles x 4 n8-tiles).
#define KC      64
#define NCH     (MM / KC)          // 32
#define T_A     16384              // one split tile: 128 rows x 128 B
#define ST_SZ   (4 * T_A)          // Ah, Al, Bh, Bl = 64 KB
#define STAGES  3
#define SM_GEMM (STAGES * ST_SZ)   // 192 KB

__device__ __forceinline__ void load_chunk(
    uint32_t st,
    const __nv_bfloat16* __restrict__ Ah, const __nv_bfloat16* __restrict__ Al,
    const __nv_bfloat16* __restrict__ Bh, const __nv_bfloat16* __restrict__ Bl,
    int m0, int n0, int k0, int tid)
{
#pragma unroll
    for (int t = 0; t < 16; ++t) {
        int idx  = tid + t * 256;          // 4096 x 16B
        int tile = idx >> 10;              // 0:Ah 1:Al 2:Bh 3:Bl
        int r    = (idx >> 3) & 127;
        int seg  = idx & 7;
        const __nv_bfloat16* src;
        int rb;
        if      (tile == 0) { src = Ah; rb = m0; }
        else if (tile == 1) { src = Al; rb = m0; }
        else if (tile == 2) { src = Bh; rb = n0; }
        else                { src = Bl; rb = n0; }
        cp16(st + tile * T_A + sw128(r * 128 + seg * 16),
             src + (size_t)(rb + r) * MM + k0 + seg * 8);
    }
}

// WRITEMODE 0: fp32 into g_pad interior.  1: bf16 hi/lo split into outH/outL.
template <int WRITEMODE>
__global__ __launch_bounds__(256, 1) void gemm_hmma_kernel(
    const __nv_bfloat16* __restrict__ Ah, const __nv_bfloat16* __restrict__ Al,
    const __nv_bfloat16* __restrict__ Bh, const __nv_bfloat16* __restrict__ Bl,
    float* __restrict__ outF, __nv_bfloat16* __restrict__ outH,
    __nv_bfloat16* __restrict__ outL)
{
    extern __shared__ char smem[];
    uint32_t sb = smem_u32(smem);
    int tid = threadIdx.x, wid = tid >> 5, lane = tid & 31;
    int m0 = blockIdx.y * 128, n0 = blockIdx.x * 128;
    int wm = wid & 1, wn = wid >> 1;       // warp grid 2(m) x 4(n)

    float acc[4][4][4];
#pragma unroll
    for (int i = 0; i < 4; i++)
#pragma unroll
        for (int j = 0; j < 4; j++)
#pragma unroll
            for (int q = 0; q < 4; q++) acc[i][j][q] = 0.0f;

    // lane-constant ldmatrix addressing
    int aRow  = wm * 64 + (lane & 7) + ((lane >> 3) & 1) * 8;   // + mt*16
    int aSegB = lane >> 4;                                      // + ks*2
    uint32_t aXor  = (uint32_t)(aRow & 7) << 4;
    uint32_t aBase = (uint32_t)aRow * 128;
    int bRow  = wn * 32 + (lane & 7) + ((lane >> 4) & 1) * 8;   // + pair*16
    int bSegB = (lane >> 3) & 1;                                // + ks*2
    uint32_t bXor  = (uint32_t)(bRow & 7) << 4;
    uint32_t bBase = (uint32_t)bRow * 128;

    load_chunk(sb + 0 * ST_SZ, Ah, Al, Bh, Bl, m0, n0, 0 * KC, tid); CP_COMMIT();
    load_chunk(sb + 1 * ST_SZ, Ah, Al, Bh, Bl, m0, n0, 1 * KC, tid); CP_COMMIT();
    load_chunk(sb + 2 * ST_SZ, Ah, Al, Bh, Bl, m0, n0, 2 * KC, tid); CP_COMMIT();

    for (int c = 0; c < NCH; ++c) {
        if      (c <= NCH - 3) CP_WAIT(2);
        else if (c == NCH - 2) CP_WAIT(1);
        else                   CP_WAIT(0);
        __syncthreads();

        uint32_t st = sb + (c % STAGES) * ST_SZ;
        uint32_t sAh = st, sAl = st + T_A, sBh = st + 2 * T_A, sBl = st + 3 * T_A;

#pragma unroll
        for (int ks = 0; ks < 4; ++ks) {
            uint32_t ah[4][4], al[4][4], bh[2][4], bl[2][4];
            uint32_t aSegOff = (uint32_t)(((ks * 2 + aSegB) * 16) ^ aXor);
            uint32_t bSegOff = (uint32_t)(((ks * 2 + bSegB) * 16) ^ bXor);
#pragma unroll
            for (int mt = 0; mt < 4; ++mt) {
                uint32_t off = aBase + mt * 2048 + aSegOff;
                ldsm4(ah[mt][0], ah[mt][1], ah[mt][2], ah[mt][3], sAh + off);
                ldsm4(al[mt][0], al[mt][1], al[mt][2], al[mt][3], sAl + off);
            }
#pragma unroll
            for (int p = 0; p < 2; ++p) {
                uint32_t off = bBase + p * 2048 + bSegOff;
                ldsm4(bh[p][0], bh[p][1], bh[p][2], bh[p][3], sBh + off);
                ldsm4(bl[p][0], bl[p][1], bl[p][2], bl[p][3], sBl + off);
            }
#pragma unroll
            for (int mt = 0; mt < 4; ++mt)
#pragma unroll
                for (int nt = 0; nt < 4; ++nt) {
                    const uint32_t* pbh = &bh[nt >> 1][(nt & 1) * 2];
                    const uint32_t* pbl = &bl[nt >> 1][(nt & 1) * 2];
                    mma16816(acc[mt][nt], ah[mt], pbh);
                    mma16816(acc[mt][nt], ah[mt], pbl);
                    mma16816(acc[mt][nt], al[mt], pbh);
                }
        }
        __syncthreads();
        if (c + STAGES < NCH) {
            load_chunk(sb + (c % STAGES) * ST_SZ, Ah, Al, Bh, Bl,
                       m0, n0, (c + STAGES) * KC, tid);
            CP_COMMIT();
        } else {
            CP_COMMIT();   // keep group counting uniform
        }
    }

    // epilogue: c-frag (row = lane/4 (+8), col = (lane%4)*2 (+1))
#pragma unroll
    for (int mt = 0; mt < 4; ++mt)
#pragma unroll
        for (int nt = 0; nt < 4; ++nt) {
#pragma unroll
            for (int h = 0; h < 2; ++h) {
                int row = m0 + wm * 64 + mt * 16 + (lane >> 2) + h * 8;
                int col = n0 + wn * 32 + nt * 8 + (lane & 3) * 2;
                float v0 = acc[mt][nt][h * 2 + 0];
                float v1 = acc[mt][nt][h * 2 + 1];
                if (WRITEMODE == 0) {
                    size_t o = (size_t)(row + PADB) * PP + col + PADB;
                    outF[o]     = v0;
                    outF[o + 1] = v1;
                } else {
                    __nv_bfloat16 h0 = __float2bfloat16(v0);
                    __nv_bfloat16 h1 = __float2bfloat16(v1);
                    __nv_bfloat16 l0 = __float2bfloat16(v0 - __bfloat162float(h0));
                    __nv_bfloat16 l1 = __float2bfloat16(v1 - __bfloat162float(h1));
                    size_t o = (size_t)row * MM + col;
                    __nv_bfloat162 hp; hp.x = h0; hp.y = h1;
                    __nv_bfloat162 lp; lp.x = l0; lp.y = l1;
                    *(__nv_bfloat162*)&outH[o] = hp;
                    *(__nv_bfloat162*)&outL[o] = lp;
                }
            }
        }
}

// ------------------------------- radon etc --------------------------------
__global__ void radon_kernel() {
    int a = blockIdx.y;
    int x = blockIdx.x * 128 + threadIdx.x;
    if (x >= PP) return;

    float ang = (float)(3.141592653589793 * (double)a / 31.0);
    float ca = cosf(ang);
    float sa = sinf(ang);
    const float cen = (float)(PP / 2);
    float c1 = cen * (ca + sa - 1.0f);
    float c2 = cen * (ca - sa - 1.0f);

    float xf = (float)x;
    float bx = ca * xf - c1;
    float by = -sa * xf - c2;

    int ys = blockIdx.z * YCHUNK;
    int ye = min(PP, ys + YCHUNK);

    float acc = 0.0f;
    for (int y = ys; y < ye; ++y) {
        float yf  = (float)y;
        float xin = fmaf(sa, yf, bx);
        float yin = fmaf(ca, yf, by);
        float fx = floorf(xin);
        float fy = floorf(yin);
        float wx = xin - fx;
        float wy = yin - fy;
        int x0 = (int)fx % PP; if (x0 < 0) x0 += PP;
        int y0 = (int)fy % PP; if (y0 < 0) y0 += PP;
        int x1 = x0 + 1; if (x1 == PP) x1 = 0;
        int y1 = y0 + 1; if (y1 == PP) y1 = 0;
        const float* r0 = g_pad + (size_t)y0 * PP;
        const float* r1 = g_pad + (size_t)y1 * PP;
        float v00 = __ldg(r0 + x0);
        float v01 = __ldg(r0 + x1);
        float v10 = __ldg(r1 + x0);
        float v11 = __ldg(r1 + x1);
        float top = (1.0f - wx) * v00 + wx * v01;
        float bot = (1.0f - wx) * v10 + wx * v11;
        acc += (1.0f - wy) * top + wy * bot;
    }
    g_lpart[(size_t)blockIdx.z * TOT + a * PP + x] = acc;
}

__global__ void reduce_max_kernel() {
    __shared__ float smax[256];
    int idx = blockIdx.x * 256 + threadIdx.x;
    float v = -__int_as_float(0x7f800000);
    if (idx < TOT) {
        float s = 0.0f;
#pragma unroll
        for (int p = 0; p < YSPLIT; p++) s += g_lpart[(size_t)p * TOT + idx];
        g_lines[idx] = s;
        v = s;
    }
    smax[threadIdx.x] = v;
    __syncthreads();
    for (int o = 128; o > 0; o >>= 1) {
        if (threadIdx.x < o)
            smax[threadIdx.x] = fmaxf(smax[threadIdx.x], smax[threadIdx.x + o]);
        __syncthreads();
    }
    if (threadIdx.x == 0) {
        unsigned u = __float_as_uint(smax[0]);
        unsigned enc = (u & 0x80000000u) ? ~u : (u | 0x80000000u);
        atomicMax(&g_maxbits, enc);
    }
}

__global__ void normalize_kernel(float* __restrict__ out) {
    int idx = blockIdx.x * 256 + threadIdx.x;
    if (idx >= TOT) return;
    unsigned u = g_maxbits;
    float mx = (u & 0x80000000u) ? __uint_as_float(u & 0x7fffffffu)
                                 : __uint_as_float(~u);
    int x = idx >> 5;
    int a = idx & 31;
    out[idx] = g_lines[a * PP + x] / mx;
}

// ---------------------------------------------------------------------------
extern "C" void kernel_launch(void* const* d_in, const int* in_sizes, int n_in,
                              void* d_out, int out_size) {
    const float* img = (const float*)d_in[0];
    float* out = (float*)d_out;

    static int s_init = 0;
    if (!s_init) {
        cudaFuncSetAttribute(gemm_hmma_kernel<0>,
                             cudaFuncAttributeMaxDynamicSharedMemorySize, SM_GEMM);
        cudaFuncSetAttribute(gemm_hmma_kernel<1>,
                             cudaFuncAttributeMaxDynamicSharedMemorySize, SM_GEMM);
        s_init = 1;
    }

    init_kernel<<<(PP * PP + 255) / 256, 256>>>();
    gen_dct_kernel<<<(MM * MM + 255) / 256, 256>>>();
    transpose_split_kernel<<<dim3(64, 64), dim3(32, 8)>>>(img);

    __nv_bfloat16 *pCh, *pCl, *pXTh, *pXTl, *pTh, *pTl;
    cudaGetSymbolAddress((void**)&pCh,  g_Ch);
    cudaGetSymbolAddress((void**)&pCl,  g_Cl);
    cudaGetSymbolAddress((void**)&pXTh, g_XTh);
    cudaGetSymbolAddress((void**)&pXTl, g_XTl);
    cudaGetSymbolAddress((void**)&pTh,  g_Th);
    cudaGetSymbolAddress((void**)&pTl,  g_Tl);
    float* pPad;
    cudaGetSymbolAddress((void**)&pPad, g_pad);

    dim3 gg(MM / 128, MM / 128);
    // tmp = C @ X : A = C, B = X^T (both K-major)
    gemm_hmma_kernel<1><<<gg, 256, SM_GEMM>>>(pCh, pCl, pXTh, pXTl,
                                              nullptr, pTh, pTl);
    // pad interior = tmp @ C^T : A = tmp, B = C
    gemm_hmma_kernel<0><<<gg, 256, SM_GEMM>>>(pTh, pTl, pCh, pCl,
                                              pPad, nullptr, nullptr);

    dim3 rg((PP + 127) / 128, NANG, YSPLIT);
    radon_kernel<<<rg, 128>>>();

    reduce_max_kernel<<<(TOT + 255) / 256, 256>>>();
    normalize_kernel<<<(TOT + 255) / 256, 256>>>(out);
}

// round 4
// speedup vs baseline: 1.8965x; 1.0995x over previous
#include <cuda_runtime.h>
#include <cuda_bf16.h>
#include <cstdint>

// ---------------------------------------------------------------------------
// image_prj: D = dct2(image) [2048x2048, ortho] -> pad to 2198x2198 ->
// 32-angle radon (bilinear, WRAP) -> lines^T / max
// GEMMs: mma.sync bf16x3 split.  Radon: smem-tiled bilinear gather.
// ---------------------------------------------------------------------------

#define MM    2048
#define PP    2198
#define PADB  75
#define NANG  32
#define TOT   (NANG * PP)
#define NYT   35                   // y-tiles of 64 (35*64 = 2240 >= 2198)
#define NXT   35

__device__ __nv_bfloat16 g_Ch[MM * MM], g_Cl[MM * MM];
__device__ __nv_bfloat16 g_XTh[MM * MM], g_XTl[MM * MM];
__device__ __nv_bfloat16 g_Th[MM * MM], g_Tl[MM * MM];
__device__ float    g_pad[PP * PP];
__device__ float    g_lpart[NYT * TOT];      // ~9.9 MB
__device__ float    g_lines[TOT];
__device__ unsigned g_maxbits;

// ------------------------------ PTX helpers -------------------------------
__device__ __forceinline__ uint32_t smem_u32(const void* p) {
    uint32_t a;
    asm("{ .reg .u64 t; cvta.to.shared.u64 t, %1; cvt.u32.u64 %0, t; }"
        : "=r"(a) : "l"(p));
    return a;
}
#define CP_COMMIT() asm volatile("cp.async.commit_group;" ::: "memory")
#define CP_WAIT(n)  asm volatile("cp.async.wait_group %0;" :: "n"(n) : "memory")

__device__ __forceinline__ void cp16(uint32_t dst, const void* src) {
    asm volatile("cp.async.cg.shared.global [%0], [%1], 16;"
                 :: "r"(dst), "l"(src) : "memory");
}
__device__ __forceinline__ void ldsm4(uint32_t& r0, uint32_t& r1,
                                      uint32_t& r2, uint32_t& r3, uint32_t a) {
    asm volatile("ldmatrix.sync.aligned.m8n8.x4.shared.b16 {%0,%1,%2,%3}, [%4];"
                 : "=r"(r0), "=r"(r1), "=r"(r2), "=r"(r3) : "r"(a));
}
__device__ __forceinline__ void mma16816(float* d, const uint32_t* a,
                                         const uint32_t* b) {
    asm volatile("mma.sync.aligned.m16n8k16.row.col.f32.bf16.bf16.f32 "
                 "{%0,%1,%2,%3}, {%4,%5,%6,%7}, {%8,%9}, {%0,%1,%2,%3};"
                 : "+f"(d[0]), "+f"(d[1]), "+f"(d[2]), "+f"(d[3])
                 : "r"(a[0]), "r"(a[1]), "r"(a[2]), "r"(a[3]),
                   "r"(b[0]), "r"(b[1]));
}
__device__ __forceinline__ uint32_t sw128(uint32_t b) { return b ^ ((b >> 3) & 0x70); }

// --------------------------- small prep kernels ---------------------------
__global__ void init_kernel() {
    int idx = blockIdx.x * 256 + threadIdx.x;
    if (idx < PP * PP) g_pad[idx] = 0.0f;
    if (idx == 0) g_maxbits = 0u;
}

__global__ void gen_dct_kernel() {
    int idx = blockIdx.x * 256 + threadIdx.x;
    if (idx >= MM * MM) return;
    int k = idx >> 11;
    int n = idx & (MM - 1);
    int r = ((2 * n + 1) * k) & (4 * MM - 1);
    float t = (float)r * (1.0f / (2.0f * MM));
    float c = cospif(t);
    float s = (k == 0) ? 0.022097086912079608f : 0.03125f;
    float v = s * c;
    __nv_bfloat16 h = __float2bfloat16(v);
    g_Ch[idx] = h;
    g_Cl[idx] = __float2bfloat16(v - __bfloat162float(h));
}

__global__ void transpose_split_kernel(const float* __restrict__ img) {
    __shared__ float tile[32][33];
    int bx = blockIdx.x * 32, by = blockIdx.y * 32;
    int tx = threadIdx.x, ty = threadIdx.y;
#pragma unroll
    for (int i = 0; i < 4; i++)
        tile[ty + i * 8][tx] = img[(size_t)(by + ty + i * 8) * MM + bx + tx];
    __syncthreads();
#pragma unroll
    for (int i = 0; i < 4; i++) {
        float v = tile[tx][ty + i * 8];
        __nv_bfloat16 h = __float2bfloat16(v);
        size_t o = (size_t)(bx + ty + i * 8) * MM + by + tx;
        g_XTh[o] = h;
        g_XTl[o] = __float2bfloat16(v - __bfloat162float(h));
    }
}

// ------------------------------ HMMA GEMM ---------------------------------
#define KC      64
#define NCH     (MM / KC)
#define T_A     16384
#define ST_SZ   (4 * T_A)
#define STAGES  3
#define SM_GEMM (STAGES * ST_SZ)

__device__ __forceinline__ void load_chunk(
    uint32_t st,
    const __nv_bfloat16* __restrict__ Ah, const __nv_bfloat16* __restrict__ Al,
    const __nv_bfloat16* __restrict__ Bh, const __nv_bfloat16* __restrict__ Bl,
    int m0, int n0, int k0, int tid)
{
#pragma unroll
    for (int t = 0; t < 16; ++t) {
        int idx  = tid + t * 256;
        int tile = idx >> 10;
        int r    = (idx >> 3) & 127;
        int seg  = idx & 7;
        const __nv_bfloat16* src;
        int rb;
        if      (tile == 0) { src = Ah; rb = m0; }
        else if (tile == 1) { src = Al; rb = m0; }
        else if (tile == 2) { src = Bh; rb = n0; }
        else                { src = Bl; rb = n0; }
        cp16(st + tile * T_A + sw128(r * 128 + seg * 16),
             src + (size_t)(rb + r) * MM + k0 + seg * 8);
    }
}

template <int WRITEMODE>
__global__ __launch_bounds__(256, 1) void gemm_hmma_kernel(
    const __nv_bfloat16* __restrict__ Ah, const __nv_bfloat16* __restrict__ Al,
    const __nv_bfloat16* __restrict__ Bh, const __nv_bfloat16* __restrict__ Bl,
    float* __restrict__ outF, __nv_bfloat16* __restrict__ outH,
    __nv_bfloat16* __restrict__ outL)
{
    extern __shared__ char smem[];
    uint32_t sb = smem_u32(smem);
    int tid = threadIdx.x, wid = tid >> 5, lane = tid & 31;
    int m0 = blockIdx.y * 128, n0 = blockIdx.x * 128;
    int wm = wid & 1, wn = wid >> 1;

    float acc[4][4][4];
#pragma unroll
    for (int i = 0; i < 4; i++)
#pragma unroll
        for (int j = 0; j < 4; j++)
#pragma unroll
            for (int q = 0; q < 4; q++) acc[i][j][q] = 0.0f;

    int aRow  = wm * 64 + (lane & 7) + ((lane >> 3) & 1) * 8;
    int aSegB = lane >> 4;
    uint32_t aXor  = (uint32_t)(aRow & 7) << 4;
    uint32_t aBase = (uint32_t)aRow * 128;
    int bRow  = wn * 32 + (lane & 7) + ((lane >> 4) & 1) * 8;
    int bSegB = (lane >> 3) & 1;
    uint32_t bXor  = (uint32_t)(bRow & 7) << 4;
    uint32_t bBase = (uint32_t)bRow * 128;

    load_chunk(sb + 0 * ST_SZ, Ah, Al, Bh, Bl, m0, n0, 0 * KC, tid); CP_COMMIT();
    load_chunk(sb + 1 * ST_SZ, Ah, Al, Bh, Bl, m0, n0, 1 * KC, tid); CP_COMMIT();
    load_chunk(sb + 2 * ST_SZ, Ah, Al, Bh, Bl, m0, n0, 2 * KC, tid); CP_COMMIT();

    for (int c = 0; c < NCH; ++c) {
        if      (c <= NCH - 3) CP_WAIT(2);
        else if (c == NCH - 2) CP_WAIT(1);
        else                   CP_WAIT(0);
        __syncthreads();

        uint32_t st = sb + (c % STAGES) * ST_SZ;
        uint32_t sAh = st, sAl = st + T_A, sBh = st + 2 * T_A, sBl = st + 3 * T_A;

#pragma unroll
        for (int ks = 0; ks < 4; ++ks) {
            uint32_t ah[4][4], al[4][4], bh[2][4], bl[2][4];
            uint32_t aSegOff = (uint32_t)(((ks * 2 + aSegB) * 16) ^ aXor);
            uint32_t bSegOff = (uint32_t)(((ks * 2 + bSegB) * 16) ^ bXor);
#pragma unroll
            for (int mt = 0; mt < 4; ++mt) {
                uint32_t off = aBase + mt * 2048 + aSegOff;
                ldsm4(ah[mt][0], ah[mt][1], ah[mt][2], ah[mt][3], sAh + off);
                ldsm4(al[mt][0], al[mt][1], al[mt][2], al[mt][3], sAl + off);
            }
#pragma unroll
            for (int p = 0; p < 2; ++p) {
                uint32_t off = bBase + p * 2048 + bSegOff;
                ldsm4(bh[p][0], bh[p][1], bh[p][2], bh[p][3], sBh + off);
                ldsm4(bl[p][0], bl[p][1], bl[p][2], bl[p][3], sBl + off);
            }
#pragma unroll
            for (int mt = 0; mt < 4; ++mt)
#pragma unroll
                for (int nt = 0; nt < 4; ++nt) {
                    const uint32_t* pbh = &bh[nt >> 1][(nt & 1) * 2];
                    const uint32_t* pbl = &bl[nt >> 1][(nt & 1) * 2];
                    mma16816(acc[mt][nt], ah[mt], pbh);
                    mma16816(acc[mt][nt], ah[mt], pbl);
                    mma16816(acc[mt][nt], al[mt], pbh);
                }
        }
        __syncthreads();
        if (c + STAGES < NCH) {
            load_chunk(sb + (c % STAGES) * ST_SZ, Ah, Al, Bh, Bl,
                       m0, n0, (c + STAGES) * KC, tid);
            CP_COMMIT();
        } else {
            CP_COMMIT();
        }
    }

#pragma unroll
    for (int mt = 0; mt < 4; ++mt)
#pragma unroll
        for (int nt = 0; nt < 4; ++nt) {
#pragma unroll
            for (int h = 0; h < 2; ++h) {
                int row = m0 + wm * 64 + mt * 16 + (lane >> 2) + h * 8;
                int col = n0 + wn * 32 + nt * 8 + (lane & 3) * 2;
                float v0 = acc[mt][nt][h * 2 + 0];
                float v1 = acc[mt][nt][h * 2 + 1];
                if (WRITEMODE == 0) {
                    size_t o = (size_t)(row + PADB) * PP + col + PADB;
                    outF[o]     = v0;
                    outF[o + 1] = v1;
                } else {
                    __nv_bfloat16 h0 = __float2bfloat16(v0);
                    __nv_bfloat16 h1 = __float2bfloat16(v1);
                    __nv_bfloat16 l0 = __float2bfloat16(v0 - __bfloat162float(h0));
                    __nv_bfloat16 l1 = __float2bfloat16(v1 - __bfloat162float(h1));
                    size_t o = (size_t)row * MM + col;
                    __nv_bfloat162 hp; hp.x = h0; hp.y = h1;
                    __nv_bfloat162 lp; lp.x = l0; lp.y = l1;
                    *(__nv_bfloat162*)&outH[o] = hp;
                    *(__nv_bfloat162*)&outL[o] = lp;
                }
            }
        }
}

// ------------------------------ tiled radon --------------------------------
// Block = (x-tile 64, y-tile 64, angle). Footprint of the rotated 64x64 tile
// (<= 94x94 floats) is staged in smem (stride 97, bank-safe); bilinear reads
// hit smem. floor/weights computed on GLOBAL coords (identical fp expressions
// to the validated gather kernel); smem index via exact integer subtraction.
#define RSW 97     // smem row stride (odd -> conflict-free columns)
#define RSH 96

__global__ __launch_bounds__(256) void radon_tiled_kernel() {
    __shared__ float sm[RSH * RSW];
    __shared__ float red[256];

    int a  = blockIdx.z;
    int x0 = blockIdx.x * 64;
    int y0 = blockIdx.y * 64;
    int tid = threadIdx.x, wid = tid >> 5, lane = tid & 31;

    float ang = (float)(3.141592653589793 * (double)a / 31.0);
    float ca = cosf(ang);
    float sa = sinf(ang);
    const float cen = (float)(PP / 2);
    float c1 = cen * (ca + sa - 1.0f);
    float c2 = cen * (ca - sa - 1.0f);

    // footprint bounds from tile corners (xin/yin linear -> extremes at corners)
    float xf0 = (float)x0, xf1 = (float)(x0 + 63);
    float yf0 = (float)y0, yf1 = (float)(y0 + 63);
    float u00 = ca * xf0 + sa * yf0 - c1, u01 = ca * xf0 + sa * yf1 - c1;
    float u10 = ca * xf1 + sa * yf0 - c1, u11 = ca * xf1 + sa * yf1 - c1;
    float v00 = -sa * xf0 + ca * yf0 - c2, v01 = -sa * xf0 + ca * yf1 - c2;
    float v10 = -sa * xf1 + ca * yf0 - c2, v11 = -sa * xf1 + ca * yf1 - c2;
    float umin = fminf(fminf(u00, u01), fminf(u10, u11));
    float umax = fmaxf(fmaxf(u00, u01), fmaxf(u10, u11));
    float vmin = fminf(fminf(v00, v01), fminf(v10, v11));
    float vmax = fmaxf(fmaxf(v00, v01), fmaxf(v10, v11));

    int u0i = (int)floorf(umin) - 1;
    int v0i = (int)floorf(vmin) - 1;
    int W = (int)floorf(umax) + 2 - u0i + 1;   // covers ix..ix+1 (+safety)
    int H = (int)floorf(vmax) + 2 - v0i + 1;

    int u0m = u0i % PP; if (u0m < 0) u0m += PP;
    int v0m = v0i % PP; if (v0m < 0) v0m += PP;

    // cooperative footprint load, coalesced along columns
    for (int r = wid; r < H; r += 8) {
        int rm = v0m + r; if (rm >= PP) rm -= PP;
        const float* rowp = g_pad + (size_t)rm * PP;
        for (int c = lane; c < W; c += 32) {
            int cm = u0m + c; if (cm >= PP) cm -= PP;
            sm[r * RSW + c] = __ldg(rowp + cm);
        }
    }
    __syncthreads();

    // samples: 64 x-lanes x 4 y-subgroups x 16 y each
    int xl   = tid & 63;
    int ysub = tid >> 6;
    int x    = x0 + xl;
    float xf = (float)x;
    float bx = ca * xf - c1;
    float by = -sa * xf - c2;

    int ybeg = y0 + ysub * 16;
    int ycnt = min(16, PP - ybeg); if (ycnt < 0) ycnt = 0;

    float acc = 0.0f;
    float yf = (float)ybeg;
    for (int i = 0; i < ycnt; ++i) {
        float xin = fmaf(sa, yf, bx);
        float yin = fmaf(ca, yf, by);
        float fx = floorf(xin);
        float fy = floorf(yin);
        float wx = xin - fx;
        float wy = yin - fy;
        int il = (int)fx - u0i;
        int jl = (int)fy - v0i;
        const float* p = sm + jl * RSW + il;
        float s00 = p[0], s01 = p[1], s10 = p[RSW], s11 = p[RSW + 1];
        float top = (1.0f - wx) * s00 + wx * s01;
        float bot = (1.0f - wx) * s10 + wx * s11;
        acc += (1.0f - wy) * top + wy * bot;
        yf += 1.0f;
    }

    __syncthreads();
    red[ysub * 64 + xl] = acc;
    __syncthreads();
    if (tid < 64) {
        float s = ((red[tid] + red[64 + tid]) + red[128 + tid]) + red[192 + tid];
        int xo = x0 + tid;
        if (xo < PP)
            g_lpart[(size_t)blockIdx.y * TOT + a * PP + xo] = s;
    }
}

// --------------------------- reduce / normalize ----------------------------
__global__ void reduce_max_kernel() {
    __shared__ float smax[256];
    int idx = blockIdx.x * 256 + threadIdx.x;
    float v = -__int_as_float(0x7f800000);
    if (idx < TOT) {
        float s = 0.0f;
        for (int p = 0; p < NYT; p++) s += g_lpart[(size_t)p * TOT + idx];
        g_lines[idx] = s;
        v = s;
    }
    smax[threadIdx.x] = v;
    __syncthreads();
    for (int o = 128; o > 0; o >>= 1) {
        if (threadIdx.x < o)
            smax[threadIdx.x] = fmaxf(smax[threadIdx.x], smax[threadIdx.x + o]);
        __syncthreads();
    }
    if (threadIdx.x == 0) {
        unsigned u = __float_as_uint(smax[0]);
        unsigned enc = (u & 0x80000000u) ? ~u : (u | 0x80000000u);
        atomicMax(&g_maxbits, enc);
    }
}

__global__ void normalize_kernel(float* __restrict__ out) {
    int idx = blockIdx.x * 256 + threadIdx.x;
    if (idx >= TOT) return;
    unsigned u = g_maxbits;
    float mx = (u & 0x80000000u) ? __uint_as_float(u & 0x7fffffffu)
                                 : __uint_as_float(~u);
    int x = idx >> 5;
    int a = idx & 31;
    out[idx] = g_lines[a * PP + x] / mx;
}

// ---------------------------------------------------------------------------
extern "C" void kernel_launch(void* const* d_in, const int* in_sizes, int n_in,
                              void* d_out, int out_size) {
    const float* img = (const float*)d_in[0];
    float* out = (float*)d_out;

    static int s_init = 0;
    if (!s_init) {
        cudaFuncSetAttribute(gemm_hmma_kernel<0>,
                             cudaFuncAttributeMaxDynamicSharedMemorySize, SM_GEMM);
        cudaFuncSetAttribute(gemm_hmma_kernel<1>,
                             cudaFuncAttributeMaxDynamicSharedMemorySize, SM_GEMM);
        s_init = 1;
    }

    init_kernel<<<(PP * PP + 255) / 256, 256>>>();
    gen_dct_kernel<<<(MM * MM + 255) / 256, 256>>>();
    transpose_split_kernel<<<dim3(64, 64), dim3(32, 8)>>>(img);

    __nv_bfloat16 *pCh, *pCl, *pXTh, *pXTl, *pTh, *pTl;
    cudaGetSymbolAddress((void**)&pCh,  g_Ch);
    cudaGetSymbolAddress((void**)&pCl,  g_Cl);
    cudaGetSymbolAddress((void**)&pXTh, g_XTh);
    cudaGetSymbolAddress((void**)&pXTl, g_XTl);
    cudaGetSymbolAddress((void**)&pTh,  g_Th);
    cudaGetSymbolAddress((void**)&pTl,  g_Tl);
    float* pPad;
    cudaGetSymbolAddress((void**)&pPad, g_pad);

    dim3 gg(MM / 128, MM / 128);
    gemm_hmma_kernel<1><<<gg, 256, SM_GEMM>>>(pCh, pCl, pXTh, pXTl,
                                              nullptr, pTh, pTl);
    gemm_hmma_kernel<0><<<gg, 256, SM_GEMM>>>(pTh, pTl, pCh, pCl,
                                              pPad, nullptr, nullptr);

    dim3 rg(NXT, NYT, NANG);
    radon_tiled_kernel<<<rg, 256>>>();

    reduce_max_kernel<<<(TOT + 255) / 256, 256>>>();
    normalize_kernel<<<(TOT + 255) / 256, 256>>>(out);
}

// round 5
// speedup vs baseline: 1.9175x; 1.0110x over previous
#include <cuda_runtime.h>
#include <cuda_bf16.h>
#include <cstdint>

// ---------------------------------------------------------------------------
// image_prj: D = dct2(image) [2048x2048, ortho] -> pad to 2198x2198 ->
// 32-angle radon (bilinear, WRAP) -> lines^T / max
// GEMMs: mma.sync bf16x3 split, CTA 256x128 warp 64x64, 2-stage cp.async.
// Radon: smem-tiled bilinear gather, fully unrolled predicated inner loop.
// ---------------------------------------------------------------------------

#define MM    2048
#define PP    2198
#define PADB  75
#define NANG  32
#define TOT   (NANG * PP)
#define NYT   35
#define NXT   35

__device__ __nv_bfloat16 g_Ch[MM * MM], g_Cl[MM * MM];
__device__ __nv_bfloat16 g_XTh[MM * MM], g_XTl[MM * MM];
__device__ __nv_bfloat16 g_Th[MM * MM], g_Tl[MM * MM];
__device__ float    g_pad[PP * PP];
__device__ float    g_lpart[NYT * TOT];
__device__ float    g_lines[TOT];
__device__ unsigned g_maxbits;

// ------------------------------ PTX helpers -------------------------------
__device__ __forceinline__ uint32_t smem_u32(const void* p) {
    uint32_t a;
    asm("{ .reg .u64 t; cvta.to.shared.u64 t, %1; cvt.u32.u64 %0, t; }"
        : "=r"(a) : "l"(p));
    return a;
}
#define CP_COMMIT() asm volatile("cp.async.commit_group;" ::: "memory")
#define CP_WAIT(n)  asm volatile("cp.async.wait_group %0;" :: "n"(n) : "memory")

__device__ __forceinline__ void cp16(uint32_t dst, const void* src) {
    asm volatile("cp.async.cg.shared.global [%0], [%1], 16;"
                 :: "r"(dst), "l"(src) : "memory");
}
__device__ __forceinline__ void ldsm4(uint32_t& r0, uint32_t& r1,
                                      uint32_t& r2, uint32_t& r3, uint32_t a) {
    asm volatile("ldmatrix.sync.aligned.m8n8.x4.shared.b16 {%0,%1,%2,%3}, [%4];"
                 : "=r"(r0), "=r"(r1), "=r"(r2), "=r"(r3) : "r"(a));
}
__device__ __forceinline__ void mma16816(float* d, const uint32_t* a,
                                         const uint32_t* b) {
    asm volatile("mma.sync.aligned.m16n8k16.row.col.f32.bf16.bf16.f32 "
                 "{%0,%1,%2,%3}, {%4,%5,%6,%7}, {%8,%9}, {%0,%1,%2,%3};"
                 : "+f"(d[0]), "+f"(d[1]), "+f"(d[2]), "+f"(d[3])
                 : "r"(a[0]), "r"(a[1]), "r"(a[2]), "r"(a[3]),
                   "r"(b[0]), "r"(b[1]));
}
__device__ __forceinline__ uint32_t sw128(uint32_t b) { return b ^ ((b >> 3) & 0x70); }

// --------------------------- small prep kernels ---------------------------
__global__ void init_kernel() {
    int idx = blockIdx.x * 256 + threadIdx.x;
    if (idx < PP * PP) g_pad[idx] = 0.0f;
    if (idx == 0) g_maxbits = 0u;
}

__global__ void gen_dct_kernel() {
    int idx = blockIdx.x * 256 + threadIdx.x;
    if (idx >= MM * MM) return;
    int k = idx >> 11;
    int n = idx & (MM - 1);
    int r = ((2 * n + 1) * k) & (4 * MM - 1);
    float t = (float)r * (1.0f / (2.0f * MM));
    float c = cospif(t);
    float s = (k == 0) ? 0.022097086912079608f : 0.03125f;
    float v = s * c;
    __nv_bfloat16 h = __float2bfloat16(v);
    g_Ch[idx] = h;
    g_Cl[idx] = __float2bfloat16(v - __bfloat162float(h));
}

__global__ void transpose_split_kernel(const float* __restrict__ img) {
    __shared__ float tile[32][33];
    int bx = blockIdx.x * 32, by = blockIdx.y * 32;
    int tx = threadIdx.x, ty = threadIdx.y;
#pragma unroll
    for (int i = 0; i < 4; i++)
        tile[ty + i * 8][tx] = img[(size_t)(by + ty + i * 8) * MM + bx + tx];
    __syncthreads();
#pragma unroll
    for (int i = 0; i < 4; i++) {
        float v = tile[tx][ty + i * 8];
        __nv_bfloat16 h = __float2bfloat16(v);
        size_t o = (size_t)(bx + ty + i * 8) * MM + by + tx;
        g_XTh[o] = h;
        g_XTl[o] = __float2bfloat16(v - __bfloat162float(h));
    }
}

// ------------------------------ HMMA GEMM ---------------------------------
// CTA 256(m) x 128(n), 8 warps (4m x 2n), warp tile 64x64, K-chunk 64,
// 2-stage cp.async pipeline (2 x 96 KB).
#define KC      64
#define NCH     (MM / KC)
#define TA      32768           // A split tile: 256 rows x 128 B
#define TB      16384           // B split tile: 128 rows x 128 B
#define ST_SZ   (2 * TA + 2 * TB)
#define STAGES  2
#define SM_GEMM (STAGES * ST_SZ)

__device__ __forceinline__ void load_chunk(
    uint32_t st,
    const __nv_bfloat16* __restrict__ Ah, const __nv_bfloat16* __restrict__ Al,
    const __nv_bfloat16* __restrict__ Bh, const __nv_bfloat16* __restrict__ Bl,
    int m0, int n0, int k0, int tid)
{
#pragma unroll
    for (int t = 0; t < 24; ++t) {
        int idx = tid + t * 256;
        if (idx < 4096) {                       // A hi/lo: 2 x 256 rows x 8 segs
            int sp  = idx >> 11;
            int r   = (idx >> 3) & 255;
            int seg = idx & 7;
            const __nv_bfloat16* src = sp ? Al : Ah;
            cp16(st + sp * TA + sw128(r * 128 + seg * 16),
                 src + (size_t)(m0 + r) * MM + k0 + seg * 8);
        } else {                                // B hi/lo: 2 x 128 rows x 8 segs
            int j   = idx - 4096;
            int sp  = j >> 10;
            int r   = (j >> 3) & 127;
            int seg = j & 7;
            const __nv_bfloat16* src = sp ? Bl : Bh;
            cp16(st + 2 * TA + sp * TB + sw128(r * 128 + seg * 16),
                 src + (size_t)(n0 + r) * MM + k0 + seg * 8);
        }
    }
}

template <int WRITEMODE>
__global__ __launch_bounds__(256, 1) void gemm_hmma_kernel(
    const __nv_bfloat16* __restrict__ Ah, const __nv_bfloat16* __restrict__ Al,
    const __nv_bfloat16* __restrict__ Bh, const __nv_bfloat16* __restrict__ Bl,
    float* __restrict__ outF, __nv_bfloat16* __restrict__ outH,
    __nv_bfloat16* __restrict__ outL)
{
    extern __shared__ char smem[];
    uint32_t sb = smem_u32(smem);
    int tid = threadIdx.x, wid = tid >> 5, lane = tid & 31;
    int m0 = blockIdx.y * 256, n0 = blockIdx.x * 128;
    int wm = wid >> 1, wn = wid & 1;           // 4(m) x 2(n)

    float acc[4][8][4];
#pragma unroll
    for (int i = 0; i < 4; i++)
#pragma unroll
        for (int j = 0; j < 8; j++)
#pragma unroll
            for (int q = 0; q < 4; q++) acc[i][j][q] = 0.0f;

    int aRow  = wm * 64 + (lane & 7) + ((lane >> 3) & 1) * 8;   // + mt*16
    int aSegB = lane >> 4;
    uint32_t aXor  = (uint32_t)(aRow & 7) << 4;
    uint32_t aBase = (uint32_t)aRow * 128;
    int bRow  = wn * 64 + (lane & 7) + ((lane >> 4) & 1) * 8;   // + nt4*16
    int bSegB = (lane >> 3) & 1;
    uint32_t bXor  = (uint32_t)(bRow & 7) << 4;
    uint32_t bBase = (uint32_t)bRow * 128;

    load_chunk(sb + 0 * ST_SZ, Ah, Al, Bh, Bl, m0, n0, 0 * KC, tid); CP_COMMIT();
    load_chunk(sb + 1 * ST_SZ, Ah, Al, Bh, Bl, m0, n0, 1 * KC, tid); CP_COMMIT();

    for (int c = 0; c < NCH; ++c) {
        if (c + 1 < NCH) CP_WAIT(1);
        else             CP_WAIT(0);
        __syncthreads();

        uint32_t st = sb + (c & 1) * ST_SZ;
        uint32_t sAh = st, sAl = st + TA, sBh = st + 2 * TA, sBl = st + 2 * TA + TB;

#pragma unroll
        for (int ks = 0; ks < 4; ++ks) {
            uint32_t aSegOff = (uint32_t)(((ks * 2 + aSegB) * 16) ^ aXor);
            uint32_t bSegOff = (uint32_t)(((ks * 2 + bSegB) * 16) ^ bXor);
            uint32_t bh[4][4], bl[4][4];
#pragma unroll
            for (int p = 0; p < 4; ++p) {
                uint32_t off = bBase + p * 2048 + bSegOff;
                ldsm4(bh[p][0], bh[p][1], bh[p][2], bh[p][3], sBh + off);
                ldsm4(bl[p][0], bl[p][1], bl[p][2], bl[p][3], sBl + off);
            }
#pragma unroll
            for (int mt = 0; mt < 4; ++mt) {
                uint32_t ah[4], al[4];
                uint32_t off = aBase + mt * 2048 + aSegOff;
                ldsm4(ah[0], ah[1], ah[2], ah[3], sAh + off);
                ldsm4(al[0], al[1], al[2], al[3], sAl + off);
#pragma unroll
                for (int nt = 0; nt < 8; ++nt) {
                    const uint32_t* pbh = &bh[nt >> 1][(nt & 1) * 2];
                    const uint32_t* pbl = &bl[nt >> 1][(nt & 1) * 2];
                    mma16816(acc[mt][nt], ah, pbh);
                    mma16816(acc[mt][nt], ah, pbl);
                    mma16816(acc[mt][nt], al, pbh);
                }
            }
        }
        __syncthreads();
        if (c + 2 < NCH)
            load_chunk(sb + (c & 1) * ST_SZ, Ah, Al, Bh, Bl,
                       m0, n0, (c + 2) * KC, tid);
        CP_COMMIT();
    }

#pragma unroll
    for (int mt = 0; mt < 4; ++mt)
#pragma unroll
        for (int nt = 0; nt < 8; ++nt) {
#pragma unroll
            for (int h = 0; h < 2; ++h) {
                int row = m0 + wm * 64 + mt * 16 + (lane >> 2) + h * 8;
                int col = n0 + wn * 64 + nt * 8 + (lane & 3) * 2;
                float v0 = acc[mt][nt][h * 2 + 0];
                float v1 = acc[mt][nt][h * 2 + 1];
                if (WRITEMODE == 0) {
                    size_t o = (size_t)(row + PADB) * PP + col + PADB;
                    outF[o]     = v0;
                    outF[o + 1] = v1;
                } else {
                    __nv_bfloat16 h0 = __float2bfloat16(v0);
                    __nv_bfloat16 h1 = __float2bfloat16(v1);
                    __nv_bfloat16 l0 = __float2bfloat16(v0 - __bfloat162float(h0));
                    __nv_bfloat16 l1 = __float2bfloat16(v1 - __bfloat162float(h1));
                    size_t o = (size_t)row * MM + col;
                    __nv_bfloat162 hp; hp.x = h0; hp.y = h1;
                    __nv_bfloat162 lp; lp.x = l0; lp.y = l1;
                    *(__nv_bfloat162*)&outH[o] = hp;
                    *(__nv_bfloat162*)&outL[o] = lp;
                }
            }
        }
}

// ------------------------------ tiled radon --------------------------------
#define RSW 97
#define RSH 96

__global__ __launch_bounds__(256) void radon_tiled_kernel() {
    __shared__ float sm[RSH * RSW];
    __shared__ float red[256];

    int a  = blockIdx.z;
    int x0 = blockIdx.x * 64;
    int y0 = blockIdx.y * 64;
    int tid = threadIdx.x, wid = tid >> 5, lane = tid & 31;

    float ang = (float)(3.141592653589793 * (double)a / 31.0);
    float ca = cosf(ang);
    float sa = sinf(ang);
    const float cen = (float)(PP / 2);
    float c1 = cen * (ca + sa - 1.0f);
    float c2 = cen * (ca - sa - 1.0f);

    float xf0 = (float)x0, xf1 = (float)(x0 + 63);
    float yf0 = (float)y0, yf1 = (float)(y0 + 63);
    float u00 = ca * xf0 + sa * yf0 - c1, u01 = ca * xf0 + sa * yf1 - c1;
    float u10 = ca * xf1 + sa * yf0 - c1, u11 = ca * xf1 + sa * yf1 - c1;
    float v00 = -sa * xf0 + ca * yf0 - c2, v01 = -sa * xf0 + ca * yf1 - c2;
    float v10 = -sa * xf1 + ca * yf0 - c2, v11 = -sa * xf1 + ca * yf1 - c2;
    float umin = fminf(fminf(u00, u01), fminf(u10, u11));
    float umax = fmaxf(fmaxf(u00, u01), fmaxf(u10, u11));
    float vmin = fminf(fminf(v00, v01), fminf(v10, v11));
    float vmax = fmaxf(fmaxf(v00, v01), fmaxf(v10, v11));

    int u0i = (int)floorf(umin) - 1;
    int v0i = (int)floorf(vmin) - 1;
    int W = (int)floorf(umax) + 2 - u0i + 1;
    int H = (int)floorf(vmax) + 2 - v0i + 1;

    int u0m = u0i % PP; if (u0m < 0) u0m += PP;
    int v0m = v0i % PP; if (v0m < 0) v0m += PP;

    for (int r = wid; r < H; r += 8) {
        int rm = v0m + r; if (rm >= PP) rm -= PP;
        const float* rowp = g_pad + (size_t)rm * PP;
        for (int c = lane; c < W; c += 32) {
            int cm = u0m + c; if (cm >= PP) cm -= PP;
            sm[r * RSW + c] = __ldg(rowp + cm);
        }
    }
    __syncthreads();

    int xl   = tid & 63;
    int ysub = tid >> 6;
    int x    = x0 + xl;
    float xf = (float)x;
    float bx = ca * xf - c1;
    float by = -sa * xf - c2;

    int ybeg = y0 + ysub * 16;
    float acc0 = 0.0f, acc1 = 0.0f;

#pragma unroll
    for (int i = 0; i < 16; ++i) {
        int y = ybeg + i;
        float yf  = (float)y;
        float xin = fmaf(sa, yf, bx);
        float yin = fmaf(ca, yf, by);
        float fx = floorf(xin);
        float fy = floorf(yin);
        float wx = xin - fx;
        float wy = yin - fy;
        int il = (int)fx - u0i;
        int jl = (int)fy - v0i;
        const float* p = sm + jl * RSW + il;
        float s00 = p[0], s01 = p[1], s10 = p[RSW], s11 = p[RSW + 1];
        float top = fmaf(wx, s01 - s00, s00);
        float bot = fmaf(wx, s11 - s10, s10);
        float res = fmaf(wy, bot - top, top);
        float g = (y < PP) ? 1.0f : 0.0f;
        if (i & 1) acc1 = fmaf(g, res, acc1);
        else       acc0 = fmaf(g, res, acc0);
    }
    float acc = acc0 + acc1;

    __syncthreads();
    red[ysub * 64 + xl] = acc;
    __syncthreads();
    if (tid < 64) {
        float s = ((red[tid] + red[64 + tid]) + red[128 + tid]) + red[192 + tid];
        int xo = x0 + tid;
        if (xo < PP)
            g_lpart[(size_t)blockIdx.y * TOT + a * PP + xo] = s;
    }
}

// --------------------------- reduce / normalize ----------------------------
__global__ void reduce_max_kernel() {
    __shared__ float smax[256];
    int idx = blockIdx.x * 256 + threadIdx.x;
    float v = -__int_as_float(0x7f800000);
    if (idx < TOT) {
        float s = 0.0f;
        for (int p = 0; p < NYT; p++) s += g_lpart[(size_t)p * TOT + idx];
        g_lines[idx] = s;
        v = s;
    }
    smax[threadIdx.x] = v;
    __syncthreads();
    for (int o = 128; o > 0; o >>= 1) {
        if (threadIdx.x < o)
            smax[threadIdx.x] = fmaxf(smax[threadIdx.x], smax[threadIdx.x + o]);
        __syncthreads();
    }
    if (threadIdx.x == 0) {
        unsigned u = __float_as_uint(smax[0]);
        unsigned enc = (u & 0x80000000u) ? ~u : (u | 0x80000000u);
        atomicMax(&g_maxbits, enc);
    }
}

__global__ void normalize_kernel(float* __restrict__ out) {
    int idx = blockIdx.x * 256 + threadIdx.x;
    if (idx >= TOT) return;
    unsigned u = g_maxbits;
    float mx = (u & 0x80000000u) ? __uint_as_float(u & 0x7fffffffu)
                                 : __uint_as_float(~u);
    int x = idx >> 5;
    int a = idx & 31;
    out[idx] = g_lines[a * PP + x] / mx;
}

// ---------------------------------------------------------------------------
extern "C" void kernel_launch(void* const* d_in, const int* in_sizes, int n_in,
                              void* d_out, int out_size) {
    const float* img = (const float*)d_in[0];
    float* out = (float*)d_out;

    static int s_init = 0;
    if (!s_init) {
        cudaFuncSetAttribute(gemm_hmma_kernel<0>,
                             cudaFuncAttributeMaxDynamicSharedMemorySize, SM_GEMM);
        cudaFuncSetAttribute(gemm_hmma_kernel<1>,
                             cudaFuncAttributeMaxDynamicSharedMemorySize, SM_GEMM);
        s_init = 1;
    }

    init_kernel<<<(PP * PP + 255) / 256, 256>>>();
    gen_dct_kernel<<<(MM * MM + 255) / 256, 256>>>();
    transpose_split_kernel<<<dim3(64, 64), dim3(32, 8)>>>(img);

    __nv_bfloat16 *pCh, *pCl, *pXTh, *pXTl, *pTh, *pTl;
    cudaGetSymbolAddress((void**)&pCh,  g_Ch);
    cudaGetSymbolAddress((void**)&pCl,  g_Cl);
    cudaGetSymbolAddress((void**)&pXTh, g_XTh);
    cudaGetSymbolAddress((void**)&pXTl, g_XTl);
    cudaGetSymbolAddress((void**)&pTh,  g_Th);
    cudaGetSymbolAddress((void**)&pTl,  g_Tl);
    float* pPad;
    cudaGetSymbolAddress((void**)&pPad, g_pad);

    dim3 gg(MM / 128, MM / 256);   // 16 x 8 = 128 CTAs
    gemm_hmma_kernel<1><<<gg, 256, SM_GEMM>>>(pCh, pCl, pXTh, pXTl,
                                              nullptr, pTh, pTl);
    gemm_hmma_kernel<0><<<gg, 256, SM_GEMM>>>(pTh, pTl, pCh, pCl,
                                              pPad, nullptr, nullptr);

    dim3 rg(NXT, NYT, NANG);
    radon_tiled_kernel<<<rg, 256>>>();

    reduce_max_kernel<<<(TOT + 255) / 256, 256>>>();
    normalize_kernel<<<(TOT + 255) / 256, 256>>>(out);
}